// round 2
// baseline (speedup 1.0000x reference)
#include <cuda_runtime.h>
#include <cuda_bf16.h>

#define NG 1024
#define DG 128
#define HG 256

// ---- scratch (no allocations allowed) ----
__device__ float g_src[NG * HG];      // X @ W1a^T + b1
__device__ float g_nbr[NG * HG];      // X @ W1b^T
__device__ float g_agg[NG * HG];      // masked relu sum
__device__ float g_deg[NG];
__device__ float g_msg[NG * DG];
__device__ float g_gi[NG * 3 * DG];
__device__ float g_gh[NG * 3 * DG];

// ============================================================
// Generic C[M,N] = A[M,K] @ B^T  (B: N rows, stride ldb) + rowscale[i]*bias[c]
// BM=BN=64, BK=32, 256 threads, 4x4 microtile. M,N multiples of 64; K of 32.
// ============================================================
__global__ __launch_bounds__(256) void gemm_bias_kernel(
    const float* __restrict__ A, int lda,
    const float* __restrict__ B, int ldb,
    const float* __restrict__ bias,
    const float* __restrict__ rowscale,
    float* __restrict__ C, int ldc,
    int K)
{
    __shared__ float As[32][64];
    __shared__ float Bs[32][64];
    const int tid = threadIdx.x;
    const int tc = tid & 15;        // 0..15 -> N
    const int tr = tid >> 4;        // 0..15 -> M
    const int row0 = blockIdx.y * 64;
    const int col0 = blockIdx.x * 64;

    float acc[4][4];
#pragma unroll
    for (int r = 0; r < 4; ++r)
#pragma unroll
        for (int c = 0; c < 4; ++c) acc[r][c] = 0.f;

    for (int k0 = 0; k0 < K; k0 += 32) {
#pragma unroll
        for (int it = 0; it < 2; ++it) {
            int idx = tid + it * 256;          // 0..511
            int r   = idx >> 3;                // 0..63
            int c4  = (idx & 7) * 4;           // 0..28
            float4 va = *(const float4*)(A + (size_t)(row0 + r) * lda + k0 + c4);
            As[c4 + 0][r] = va.x; As[c4 + 1][r] = va.y;
            As[c4 + 2][r] = va.z; As[c4 + 3][r] = va.w;
            float4 vb = *(const float4*)(B + (size_t)(col0 + r) * ldb + k0 + c4);
            Bs[c4 + 0][r] = vb.x; Bs[c4 + 1][r] = vb.y;
            Bs[c4 + 2][r] = vb.z; Bs[c4 + 3][r] = vb.w;
        }
        __syncthreads();
#pragma unroll
        for (int k = 0; k < 32; ++k) {
            float4 a = *(const float4*)&As[k][tr * 4];
            float4 b = *(const float4*)&Bs[k][tc * 4];
            acc[0][0] = fmaf(a.x, b.x, acc[0][0]);
            acc[0][1] = fmaf(a.x, b.y, acc[0][1]);
            acc[0][2] = fmaf(a.x, b.z, acc[0][2]);
            acc[0][3] = fmaf(a.x, b.w, acc[0][3]);
            acc[1][0] = fmaf(a.y, b.x, acc[1][0]);
            acc[1][1] = fmaf(a.y, b.y, acc[1][1]);
            acc[1][2] = fmaf(a.y, b.z, acc[1][2]);
            acc[1][3] = fmaf(a.y, b.w, acc[1][3]);
            acc[2][0] = fmaf(a.z, b.x, acc[2][0]);
            acc[2][1] = fmaf(a.z, b.y, acc[2][1]);
            acc[2][2] = fmaf(a.z, b.z, acc[2][2]);
            acc[2][3] = fmaf(a.z, b.w, acc[2][3]);
            acc[3][0] = fmaf(a.w, b.x, acc[3][0]);
            acc[3][1] = fmaf(a.w, b.y, acc[3][1]);
            acc[3][2] = fmaf(a.w, b.z, acc[3][2]);
            acc[3][3] = fmaf(a.w, b.w, acc[3][3]);
        }
        __syncthreads();
    }

#pragma unroll
    for (int r = 0; r < 4; ++r) {
        int row = row0 + tr * 4 + r;
        float rs = rowscale ? rowscale[row] : 1.f;
#pragma unroll
        for (int c = 0; c < 4; ++c) {
            int col = col0 + tc * 4 + c;
            float v = acc[r][c];
            if (bias) v = fmaf(rs, bias[col], v);
            C[(size_t)row * ldc + col] = v;
        }
    }
}

// ============================================================
// deg[i] = number of adj[i][j] > 0   (as float)
// ============================================================
__global__ __launch_bounds__(256) void deg_kernel(const int* __restrict__ adj)
{
    const int i = blockIdx.x;
    const int tid = threadIdx.x;
    int s = 0;
    const int* row = adj + (size_t)i * NG;
#pragma unroll
    for (int it = 0; it < NG / 256; ++it)
        s += (row[tid + it * 256] > 0) ? 1 : 0;
#pragma unroll
    for (int off = 16; off > 0; off >>= 1)
        s += __shfl_down_sync(0xFFFFFFFFu, s, off);
    __shared__ int red[8];
    if ((tid & 31) == 0) red[tid >> 5] = s;
    __syncthreads();
    if (tid == 0) {
        int t = 0;
#pragma unroll
        for (int w = 0; w < 8; ++w) t += red[w];
        g_deg[i] = (float)t;
    }
}

// ============================================================
// agg[i,h] = sum_j mask[i,j] * relu(src[i,h] + nbr[j,h])   (b1 folded into src)
// CTA: 8 i-rows x 256 h.  Thread = one h, 8 register accumulators.
// Mask staged transposed in shared as floats: msh[j][t].
// ============================================================
__global__ __launch_bounds__(256) void agg_kernel(const int* __restrict__ adj)
{
    __shared__ __align__(16) float msh[NG][8];
    const int i0 = blockIdx.x * 8;
    const int tid = threadIdx.x;

    // stage mask (coalesced reads, transposed broadcast-friendly writes)
#pragma unroll
    for (int it = 0; it < 32; ++it) {
        int idx = tid + it * 256;          // 0..8191
        int t = idx >> 10;
        int j = idx & 1023;
        msh[j][t] = (adj[(size_t)(i0 + t) * NG + j] > 0) ? 1.f : 0.f;
    }
    __syncthreads();

    const int h = tid;
    float s[8], acc[8];
#pragma unroll
    for (int t = 0; t < 8; ++t) {
        s[t] = g_src[(size_t)(i0 + t) * HG + h];
        acc[t] = 0.f;
    }
    const float* nb = g_nbr + h;

#pragma unroll 4
    for (int j = 0; j < NG; ++j) {
        float nv = nb[(size_t)j * HG];
        float4 m0 = *(const float4*)&msh[j][0];
        float4 m1 = *(const float4*)&msh[j][4];
        float r;
        r = fmaxf(s[0] + nv, 0.f); acc[0] = fmaf(m0.x, r, acc[0]);
        r = fmaxf(s[1] + nv, 0.f); acc[1] = fmaf(m0.y, r, acc[1]);
        r = fmaxf(s[2] + nv, 0.f); acc[2] = fmaf(m0.z, r, acc[2]);
        r = fmaxf(s[3] + nv, 0.f); acc[3] = fmaf(m0.w, r, acc[3]);
        r = fmaxf(s[4] + nv, 0.f); acc[4] = fmaf(m1.x, r, acc[4]);
        r = fmaxf(s[5] + nv, 0.f); acc[5] = fmaf(m1.y, r, acc[5]);
        r = fmaxf(s[6] + nv, 0.f); acc[6] = fmaf(m1.z, r, acc[6]);
        r = fmaxf(s[7] + nv, 0.f); acc[7] = fmaf(m1.w, r, acc[7]);
    }

#pragma unroll
    for (int t = 0; t < 8; ++t)
        g_agg[(size_t)(i0 + t) * HG + h] = acc[t];
}

// ============================================================
// GRU elementwise:  out = (1-z)*n + z*h
// ============================================================
__global__ __launch_bounds__(256) void gru_kernel(const float* __restrict__ X,
                                                  float* __restrict__ out)
{
    int idx = blockIdx.x * 256 + threadIdx.x;   // 0..131071
    int i = idx >> 7;
    int d = idx & 127;
    const float* gi = g_gi + (size_t)i * 384;
    const float* gh = g_gh + (size_t)i * 384;
    float r = 1.f / (1.f + __expf(-(gi[d] + gh[d])));
    float z = 1.f / (1.f + __expf(-(gi[128 + d] + gh[128 + d])));
    float n = tanhf(gi[256 + d] + r * gh[256 + d]);
    float hprev = X[idx];
    out[idx] = (1.f - z) * n + z * hprev;
}

// ============================================================
extern "C" void kernel_launch(void* const* d_in, const int* in_sizes, int n_in,
                              void* d_out, int out_size)
{
    (void)in_sizes; (void)n_in; (void)out_size;
    const float* X    = (const float*)d_in[0];   // [1024,128]
    const int*   adj  = (const int*)  d_in[1];   // [1024,1024]
    const float* W1   = (const float*)d_in[2];   // [256,256]
    const float* b1   = (const float*)d_in[3];   // [256]
    const float* W2   = (const float*)d_in[4];   // [128,256]
    const float* b2   = (const float*)d_in[5];   // [128]
    const float* W_ih = (const float*)d_in[6];   // [384,128]
    const float* W_hh = (const float*)d_in[7];   // [384,128]
    const float* b_ih = (const float*)d_in[8];   // [384]
    const float* b_hh = (const float*)d_in[9];   // [384]
    float* out = (float*)d_out;

    float *src, *nbr, *agg, *deg, *msg, *gi, *gh;
    cudaGetSymbolAddress((void**)&src, g_src);
    cudaGetSymbolAddress((void**)&nbr, g_nbr);
    cudaGetSymbolAddress((void**)&agg, g_agg);
    cudaGetSymbolAddress((void**)&deg, g_deg);
    cudaGetSymbolAddress((void**)&msg, g_msg);
    cudaGetSymbolAddress((void**)&gi,  g_gi);
    cudaGetSymbolAddress((void**)&gh,  g_gh);

    // src = X @ W1[:, :128]^T + b1
    gemm_bias_kernel<<<dim3(HG / 64, NG / 64), 256>>>(X, DG, W1, 2 * DG, b1, nullptr, src, HG, DG);
    // nbr = X @ W1[:, 128:]^T
    gemm_bias_kernel<<<dim3(HG / 64, NG / 64), 256>>>(X, DG, W1 + DG, 2 * DG, nullptr, nullptr, nbr, HG, DG);
    // deg
    deg_kernel<<<NG, 256>>>(adj);
    // masked relu aggregation (dominant kernel)
    agg_kernel<<<NG / 8, 256>>>(adj);
    // msg = agg @ W2^T + deg * b2
    gemm_bias_kernel<<<dim3(DG / 64, NG / 64), 256>>>(agg, HG, W2, HG, b2, deg, msg, DG, HG);
    // gh = X @ W_hh^T + b_hh   (independent, could overlap)
    gemm_bias_kernel<<<dim3(384 / 64, NG / 64), 256>>>(X, DG, W_hh, DG, b_hh, nullptr, gh, 384, DG);
    // gi = msg @ W_ih^T + b_ih
    gemm_bias_kernel<<<dim3(384 / 64, NG / 64), 256>>>(msg, DG, W_ih, DG, b_ih, nullptr, gi, 384, DG);
    // GRU gates + output
    gru_kernel<<<(NG * DG) / 256, 256>>>(X, out);
}

// round 3
// speedup vs baseline: 1.5141x; 1.5141x over previous
#include <cuda_runtime.h>
#include <cuda_bf16.h>

#define NG 1024
#define DG 128
#define HG 256
#define JCH 8            // j-split factor
#define JW (NG / JCH)    // 128 j per chunk

// ---- scratch (no allocations allowed) ----
__device__ float g_src[NG * HG];            // X @ W1a^T + b1
__device__ float g_nbr[NG * HG];            // X @ W1b^T
__device__ float g_agg[NG * HG];            // masked relu sum
__device__ float g_part[JCH][NG * HG];      // per-j-chunk partials (8MB)
__device__ float g_deg[NG];
__device__ float g_msg[NG * DG];
__device__ float g_gi[NG * 3 * DG];
__device__ float g_gh[NG * 3 * DG];

// ============================================================
// Generic C[M,N] = A[M,K] @ B^T  (B: N rows, stride ldb) + rowscale[i]*bias[c]
// BM=BN=64, BK=32, 256 threads, 4x4 microtile. M,N multiples of 64; K of 32.
// ============================================================
__global__ __launch_bounds__(256) void gemm_bias_kernel(
    const float* __restrict__ A, int lda,
    const float* __restrict__ B, int ldb,
    const float* __restrict__ bias,
    const float* __restrict__ rowscale,
    float* __restrict__ C, int ldc,
    int K)
{
    __shared__ float As[32][64];
    __shared__ float Bs[32][64];
    const int tid = threadIdx.x;
    const int tc = tid & 15;        // 0..15 -> N
    const int tr = tid >> 4;        // 0..15 -> M
    const int row0 = blockIdx.y * 64;
    const int col0 = blockIdx.x * 64;

    float acc[4][4];
#pragma unroll
    for (int r = 0; r < 4; ++r)
#pragma unroll
        for (int c = 0; c < 4; ++c) acc[r][c] = 0.f;

    for (int k0 = 0; k0 < K; k0 += 32) {
#pragma unroll
        for (int it = 0; it < 2; ++it) {
            int idx = tid + it * 256;          // 0..511
            int r   = idx >> 3;                // 0..63
            int c4  = (idx & 7) * 4;           // 0..28
            float4 va = *(const float4*)(A + (size_t)(row0 + r) * lda + k0 + c4);
            As[c4 + 0][r] = va.x; As[c4 + 1][r] = va.y;
            As[c4 + 2][r] = va.z; As[c4 + 3][r] = va.w;
            float4 vb = *(const float4*)(B + (size_t)(col0 + r) * ldb + k0 + c4);
            Bs[c4 + 0][r] = vb.x; Bs[c4 + 1][r] = vb.y;
            Bs[c4 + 2][r] = vb.z; Bs[c4 + 3][r] = vb.w;
        }
        __syncthreads();
#pragma unroll
        for (int k = 0; k < 32; ++k) {
            float4 a = *(const float4*)&As[k][tr * 4];
            float4 b = *(const float4*)&Bs[k][tc * 4];
            acc[0][0] = fmaf(a.x, b.x, acc[0][0]);
            acc[0][1] = fmaf(a.x, b.y, acc[0][1]);
            acc[0][2] = fmaf(a.x, b.z, acc[0][2]);
            acc[0][3] = fmaf(a.x, b.w, acc[0][3]);
            acc[1][0] = fmaf(a.y, b.x, acc[1][0]);
            acc[1][1] = fmaf(a.y, b.y, acc[1][1]);
            acc[1][2] = fmaf(a.y, b.z, acc[1][2]);
            acc[1][3] = fmaf(a.y, b.w, acc[1][3]);
            acc[2][0] = fmaf(a.z, b.x, acc[2][0]);
            acc[2][1] = fmaf(a.z, b.y, acc[2][1]);
            acc[2][2] = fmaf(a.z, b.z, acc[2][2]);
            acc[2][3] = fmaf(a.z, b.w, acc[2][3]);
            acc[3][0] = fmaf(a.w, b.x, acc[3][0]);
            acc[3][1] = fmaf(a.w, b.y, acc[3][1]);
            acc[3][2] = fmaf(a.w, b.z, acc[3][2]);
            acc[3][3] = fmaf(a.w, b.w, acc[3][3]);
        }
        __syncthreads();
    }

#pragma unroll
    for (int r = 0; r < 4; ++r) {
        int row = row0 + tr * 4 + r;
        float rs = rowscale ? rowscale[row] : 1.f;
#pragma unroll
        for (int c = 0; c < 4; ++c) {
            int col = col0 + tc * 4 + c;
            float v = acc[r][c];
            if (bias) v = fmaf(rs, bias[col], v);
            C[(size_t)row * ldc + col] = v;
        }
    }
}

// ============================================================
// deg[i] = number of adj[i][j] > 0   (as float)
// ============================================================
__global__ __launch_bounds__(256) void deg_kernel(const int* __restrict__ adj)
{
    const int i = blockIdx.x;
    const int tid = threadIdx.x;
    int s = 0;
    const int* row = adj + (size_t)i * NG;
#pragma unroll
    for (int it = 0; it < NG / 256; ++it)
        s += (row[tid + it * 256] > 0) ? 1 : 0;
#pragma unroll
    for (int off = 16; off > 0; off >>= 1)
        s += __shfl_down_sync(0xFFFFFFFFu, s, off);
    __shared__ int red[8];
    if ((tid & 31) == 0) red[tid >> 5] = s;
    __syncthreads();
    if (tid == 0) {
        int t = 0;
#pragma unroll
        for (int w = 0; w < 8; ++w) t += red[w];
        g_deg[i] = (float)t;
    }
}

// ============================================================
// part[jb][i,h] = sum_{j in chunk jb} mask[i,j] * relu(src[i,h] + nbr[j,h])
// Grid: (NG/8, JCH). CTA: 8 i-rows x 256 h, j-chunk of 128.
// 4 CTAs/SM resident (regs<=64, smem 4KB) -> 32 warps/SM.
// ============================================================
__global__ __launch_bounds__(256, 4) void agg_part_kernel(const int* __restrict__ adj)
{
    __shared__ __align__(16) float msh[JW][8];
    const int i0 = blockIdx.x * 8;
    const int jb = blockIdx.y;
    const int j0 = jb * JW;
    const int tid = threadIdx.x;

    // stage mask chunk: 8 rows x 128 j  (coalesced 128-int runs)
#pragma unroll
    for (int it = 0; it < 4; ++it) {
        int idx = tid + it * 256;          // 0..1023
        int t = idx >> 7;                  // 0..7
        int j = idx & 127;
        msh[j][t] = (adj[(size_t)(i0 + t) * NG + j0 + j] > 0) ? 1.f : 0.f;
    }
    __syncthreads();

    const int h = tid;
    float s[8], acc[8];
#pragma unroll
    for (int t = 0; t < 8; ++t) {
        s[t] = g_src[(size_t)(i0 + t) * HG + h];
        acc[t] = 0.f;
    }
    const float* nb = g_nbr + (size_t)j0 * HG + h;

#pragma unroll 8
    for (int j = 0; j < JW; ++j) {
        float nv = nb[(size_t)j * HG];
        float4 m0 = *(const float4*)&msh[j][0];
        float4 m1 = *(const float4*)&msh[j][4];
        float r;
        r = fmaxf(s[0] + nv, 0.f); acc[0] = fmaf(m0.x, r, acc[0]);
        r = fmaxf(s[1] + nv, 0.f); acc[1] = fmaf(m0.y, r, acc[1]);
        r = fmaxf(s[2] + nv, 0.f); acc[2] = fmaf(m0.z, r, acc[2]);
        r = fmaxf(s[3] + nv, 0.f); acc[3] = fmaf(m0.w, r, acc[3]);
        r = fmaxf(s[4] + nv, 0.f); acc[4] = fmaf(m1.x, r, acc[4]);
        r = fmaxf(s[5] + nv, 0.f); acc[5] = fmaf(m1.y, r, acc[5]);
        r = fmaxf(s[6] + nv, 0.f); acc[6] = fmaf(m1.z, r, acc[6]);
        r = fmaxf(s[7] + nv, 0.f); acc[7] = fmaf(m1.w, r, acc[7]);
    }

    float* p = g_part[jb];
#pragma unroll
    for (int t = 0; t < 8; ++t)
        p[(size_t)(i0 + t) * HG + h] = acc[t];
}

// ============================================================
// agg = sum over JCH partials  (float4 vectorized)
// ============================================================
__global__ __launch_bounds__(256) void agg_reduce_kernel()
{
    int idx = blockIdx.x * 256 + threadIdx.x;      // over NG*HG/4
    float4 s = make_float4(0.f, 0.f, 0.f, 0.f);
#pragma unroll
    for (int c = 0; c < JCH; ++c) {
        float4 v = ((const float4*)g_part[c])[idx];
        s.x += v.x; s.y += v.y; s.z += v.z; s.w += v.w;
    }
    ((float4*)g_agg)[idx] = s;
}

// ============================================================
// GRU elementwise:  out = (1-z)*n + z*h
// ============================================================
__global__ __launch_bounds__(256) void gru_kernel(const float* __restrict__ X,
                                                  float* __restrict__ out)
{
    int idx = blockIdx.x * 256 + threadIdx.x;   // 0..131071
    int i = idx >> 7;
    int d = idx & 127;
    const float* gi = g_gi + (size_t)i * 384;
    const float* gh = g_gh + (size_t)i * 384;
    float r = 1.f / (1.f + __expf(-(gi[d] + gh[d])));
    float z = 1.f / (1.f + __expf(-(gi[128 + d] + gh[128 + d])));
    float n = tanhf(gi[256 + d] + r * gh[256 + d]);
    float hprev = X[idx];
    out[idx] = (1.f - z) * n + z * hprev;
}

// ============================================================
extern "C" void kernel_launch(void* const* d_in, const int* in_sizes, int n_in,
                              void* d_out, int out_size)
{
    (void)in_sizes; (void)n_in; (void)out_size;
    const float* X    = (const float*)d_in[0];   // [1024,128]
    const int*   adj  = (const int*)  d_in[1];   // [1024,1024]
    const float* W1   = (const float*)d_in[2];   // [256,256]
    const float* b1   = (const float*)d_in[3];   // [256]
    const float* W2   = (const float*)d_in[4];   // [128,256]
    const float* b2   = (const float*)d_in[5];   // [128]
    const float* W_ih = (const float*)d_in[6];   // [384,128]
    const float* W_hh = (const float*)d_in[7];   // [384,128]
    const float* b_ih = (const float*)d_in[8];   // [384]
    const float* b_hh = (const float*)d_in[9];   // [384]
    float* out = (float*)d_out;

    float *src, *nbr, *agg, *deg, *msg, *gi, *gh;
    cudaGetSymbolAddress((void**)&src, g_src);
    cudaGetSymbolAddress((void**)&nbr, g_nbr);
    cudaGetSymbolAddress((void**)&agg, g_agg);
    cudaGetSymbolAddress((void**)&deg, g_deg);
    cudaGetSymbolAddress((void**)&msg, g_msg);
    cudaGetSymbolAddress((void**)&gi,  g_gi);
    cudaGetSymbolAddress((void**)&gh,  g_gh);

    // src = X @ W1[:, :128]^T + b1
    gemm_bias_kernel<<<dim3(HG / 64, NG / 64), 256>>>(X, DG, W1, 2 * DG, b1, nullptr, src, HG, DG);
    // nbr = X @ W1[:, 128:]^T
    gemm_bias_kernel<<<dim3(HG / 64, NG / 64), 256>>>(X, DG, W1 + DG, 2 * DG, nullptr, nullptr, nbr, HG, DG);
    // deg
    deg_kernel<<<NG, 256>>>(adj);
    // masked relu aggregation, j-split into JCH partial slabs (dominant work)
    agg_part_kernel<<<dim3(NG / 8, JCH), 256>>>(adj);
    // sum partials
    agg_reduce_kernel<<<(NG * HG / 4) / 256, 256>>>();
    // msg = agg @ W2^T + deg * b2
    gemm_bias_kernel<<<dim3(DG / 64, NG / 64), 256>>>(agg, HG, W2, HG, b2, deg, msg, DG, HG);
    // gh = X @ W_hh^T + b_hh
    gemm_bias_kernel<<<dim3(384 / 64, NG / 64), 256>>>(X, DG, W_hh, DG, b_hh, nullptr, gh, 384, DG);
    // gi = msg @ W_ih^T + b_ih
    gemm_bias_kernel<<<dim3(384 / 64, NG / 64), 256>>>(msg, DG, W_ih, DG, b_ih, nullptr, gi, 384, DG);
    // GRU gates + output
    gru_kernel<<<(NG * DG) / 256, 256>>>(X, out);
}

// round 4
// speedup vs baseline: 1.7817x; 1.1768x over previous
#include <cuda_runtime.h>
#include <cuda_bf16.h>

#define NG 1024
#define DG 128
#define HG 256
#define JCH 8            // j-split factor
#define JW (NG / JCH)    // 128 j per chunk

typedef unsigned long long u64;

// ---- scratch (no allocations allowed) ----
__device__ float g_src[NG * HG];            // X @ W1a^T + b1
__device__ float g_nbr[NG * HG];            // X @ W1b^T
__device__ float g_agg[NG * HG];            // masked relu sum
__device__ float g_part[JCH][NG * HG];      // per-j-chunk partials (8MB)
__device__ float g_degp[JCH][NG];           // per-chunk degree partials
__device__ float g_deg[NG];
__device__ float g_msg[NG * DG];
__device__ float g_gi[NG * 3 * DG];
__device__ float g_gh[NG * 3 * DG];

// ---- packed f32x2 helpers (Blackwell) ----
__device__ __forceinline__ u64 pk2(float lo, float hi) {
    u64 r; asm("mov.b64 %0, {%1, %2};" : "=l"(r) : "f"(lo), "f"(hi)); return r;
}
__device__ __forceinline__ float2 upk(u64 v) {
    float2 r; asm("mov.b64 {%0, %1}, %2;" : "=f"(r.x), "=f"(r.y) : "l"(v)); return r;
}
__device__ __forceinline__ u64 add2(u64 a, u64 b) {
    u64 r; asm("add.rn.f32x2 %0, %1, %2;" : "=l"(r) : "l"(a), "l"(b)); return r;
}
__device__ __forceinline__ void fma2(u64& acc, u64 a, u64 b) {
    asm("fma.rn.f32x2 %0, %1, %2, %0;" : "+l"(acc) : "l"(a), "l"(b));
}

// ============================================================
// Shared GEMM tile body: C[64x64] tile at (row0,col0) of A[M,K]@B^T (+rowscale*bias)
// BK=32, 256 threads, 4x4 microtile with packed f32x2 fma.
// ============================================================
__device__ __forceinline__ void gemm_tile(
    float (*As)[64], float (*Bs)[64],
    const float* __restrict__ A, int lda,
    const float* __restrict__ B, int ldb,
    const float* __restrict__ bias,
    const float* __restrict__ rowscale,
    float* __restrict__ C, int ldc,
    int K, int row0, int col0)
{
    const int tid = threadIdx.x;
    const int tc = tid & 15;        // 0..15 -> N
    const int tr = tid >> 4;        // 0..15 -> M

    u64 acc2[4][2];
#pragma unroll
    for (int r = 0; r < 4; ++r) { acc2[r][0] = 0ull; acc2[r][1] = 0ull; }

    for (int k0 = 0; k0 < K; k0 += 32) {
#pragma unroll
        for (int it = 0; it < 2; ++it) {
            int idx = tid + it * 256;          // 0..511
            int r   = idx >> 3;                // 0..63
            int c4  = (idx & 7) * 4;           // 0..28
            float4 va = *(const float4*)(A + (size_t)(row0 + r) * lda + k0 + c4);
            As[c4 + 0][r] = va.x; As[c4 + 1][r] = va.y;
            As[c4 + 2][r] = va.z; As[c4 + 3][r] = va.w;
            float4 vb = *(const float4*)(B + (size_t)(col0 + r) * ldb + k0 + c4);
            Bs[c4 + 0][r] = vb.x; Bs[c4 + 1][r] = vb.y;
            Bs[c4 + 2][r] = vb.z; Bs[c4 + 3][r] = vb.w;
        }
        __syncthreads();
#pragma unroll
        for (int k = 0; k < 32; ++k) {
            float4 a = *(const float4*)&As[k][tr * 4];
            float4 b = *(const float4*)&Bs[k][tc * 4];
            u64 b01 = pk2(b.x, b.y);
            u64 b23 = pk2(b.z, b.w);
            u64 ar;
            ar = pk2(a.x, a.x); fma2(acc2[0][0], ar, b01); fma2(acc2[0][1], ar, b23);
            ar = pk2(a.y, a.y); fma2(acc2[1][0], ar, b01); fma2(acc2[1][1], ar, b23);
            ar = pk2(a.z, a.z); fma2(acc2[2][0], ar, b01); fma2(acc2[2][1], ar, b23);
            ar = pk2(a.w, a.w); fma2(acc2[3][0], ar, b01); fma2(acc2[3][1], ar, b23);
        }
        __syncthreads();
    }

#pragma unroll
    for (int r = 0; r < 4; ++r) {
        int row = row0 + tr * 4 + r;
        float rs = rowscale ? rowscale[row] : 1.f;
#pragma unroll
        for (int cp = 0; cp < 2; ++cp) {
            float2 f = upk(acc2[r][cp]);
            int col = col0 + tc * 4 + cp * 2;
            float v0 = f.x, v1 = f.y;
            if (bias) { v0 = fmaf(rs, bias[col], v0); v1 = fmaf(rs, bias[col + 1], v1); }
            C[(size_t)row * ldc + col]     = v0;
            C[(size_t)row * ldc + col + 1] = v1;
        }
    }
}

// ============================================================
// Generic GEMM kernel (msg, gi)
// ============================================================
__global__ __launch_bounds__(256) void gemm_bias_kernel(
    const float* __restrict__ A, int lda,
    const float* __restrict__ B, int ldb,
    const float* __restrict__ bias,
    const float* __restrict__ rowscale,
    float* __restrict__ C, int ldc,
    int K)
{
    __shared__ float As[32][64];
    __shared__ float Bs[32][64];
    gemm_tile(As, Bs, A, lda, B, ldb, bias, rowscale, C, ldc, K,
              blockIdx.y * 64, blockIdx.x * 64);
}

// ============================================================
// Fused X-GEMM: one launch computes src | nbr | gh  (all consume X, K=128)
// grid.x: 0-3 -> src (W1a + b1), 4-7 -> nbr (W1b), 8-13 -> gh (W_hh + b_hh)
// ============================================================
__global__ __launch_bounds__(256) void gemm_fusedX_kernel(
    const float* __restrict__ X,
    const float* __restrict__ W1,
    const float* __restrict__ b1,
    const float* __restrict__ W_hh,
    const float* __restrict__ b_hh,
    float* __restrict__ src,
    float* __restrict__ nbr,
    float* __restrict__ gh)
{
    __shared__ float As[32][64];
    __shared__ float Bs[32][64];
    const int bx = blockIdx.x;
    const int row0 = blockIdx.y * 64;

    const float* B; int ldb; const float* bias; float* C; int ldc; int col0;
    if (bx < 4)       { B = W1;        ldb = 2 * DG; bias = b1;   C = src; ldc = HG;  col0 = bx * 64; }
    else if (bx < 8)  { B = W1 + DG;   ldb = 2 * DG; bias = 0;    C = nbr; ldc = HG;  col0 = (bx - 4) * 64; }
    else              { B = W_hh;      ldb = DG;     bias = b_hh; C = gh;  ldc = 384; col0 = (bx - 8) * 64; }

    gemm_tile(As, Bs, X, DG, B, ldb, bias, nullptr, C, ldc, DG, row0, col0);
}

// ============================================================
// part[jb][i,h] = sum_{j in chunk jb} mask[i,j] * relu(src[i,h] + nbr[j,h])
// Grid: (NG/8, JCH). CTA: 8 i-rows x 256 h, j-chunk of 128.
// Packed f32x2: 4 row-pairs per thread. Also emits per-chunk degree partials.
// ============================================================
__global__ __launch_bounds__(256, 5) void agg_part_kernel(const int* __restrict__ adj)
{
    __shared__ __align__(16) float msh[JW][8];
    const int i0 = blockIdx.x * 8;
    const int jb = blockIdx.y;
    const int j0 = jb * JW;
    const int tid = threadIdx.x;

    // stage mask chunk: 8 rows x 128 j  (coalesced 128-int runs)
#pragma unroll
    for (int it = 0; it < 4; ++it) {
        int idx = tid + it * 256;          // 0..1023
        int t = idx >> 7;                  // 0..7
        int j = idx & 127;
        msh[j][t] = (adj[(size_t)(i0 + t) * NG + j0 + j] > 0) ? 1.f : 0.f;
    }
    __syncthreads();

    // degree partials: warp w handles row t=w
    {
        int w = tid >> 5, lane = tid & 31;
        float ds = 0.f;
#pragma unroll
        for (int k = 0; k < 4; ++k) ds += msh[lane + 32 * k][w];
#pragma unroll
        for (int off = 16; off > 0; off >>= 1)
            ds += __shfl_down_sync(0xFFFFFFFFu, ds, off);
        if (lane == 0) g_degp[jb][i0 + w] = ds;
    }

    const int h = tid;
    u64 s2[4], acc2[4];
#pragma unroll
    for (int p = 0; p < 4; ++p) {
        s2[p] = pk2(g_src[(size_t)(i0 + 2 * p) * HG + h],
                    g_src[(size_t)(i0 + 2 * p + 1) * HG + h]);
        acc2[p] = 0ull;
    }
    const float* nb = g_nbr + (size_t)j0 * HG + h;

#pragma unroll 4
    for (int j = 0; j < JW; ++j) {
        float nv = __ldg(nb + (size_t)j * HG);
        u64 nv2 = pk2(nv, nv);
        ulonglong2 ma = *(const ulonglong2*)&msh[j][0];
        ulonglong2 mb = *(const ulonglong2*)&msh[j][4];
        {
            u64 t = add2(s2[0], nv2); float2 f = upk(t);
            f.x = fmaxf(f.x, 0.f); f.y = fmaxf(f.y, 0.f);
            fma2(acc2[0], ma.x, pk2(f.x, f.y));
        }
        {
            u64 t = add2(s2[1], nv2); float2 f = upk(t);
            f.x = fmaxf(f.x, 0.f); f.y = fmaxf(f.y, 0.f);
            fma2(acc2[1], ma.y, pk2(f.x, f.y));
        }
        {
            u64 t = add2(s2[2], nv2); float2 f = upk(t);
            f.x = fmaxf(f.x, 0.f); f.y = fmaxf(f.y, 0.f);
            fma2(acc2[2], mb.x, pk2(f.x, f.y));
        }
        {
            u64 t = add2(s2[3], nv2); float2 f = upk(t);
            f.x = fmaxf(f.x, 0.f); f.y = fmaxf(f.y, 0.f);
            fma2(acc2[3], mb.y, pk2(f.x, f.y));
        }
    }

    float* p = g_part[jb];
#pragma unroll
    for (int t = 0; t < 4; ++t) {
        float2 f = upk(acc2[t]);
        p[(size_t)(i0 + 2 * t) * HG + h]     = f.x;
        p[(size_t)(i0 + 2 * t + 1) * HG + h] = f.y;
    }
}

// ============================================================
// agg = sum over JCH partials (float4); also finalizes deg.
// ============================================================
__global__ __launch_bounds__(256) void agg_reduce_kernel()
{
    int idx = blockIdx.x * 256 + threadIdx.x;      // over NG*HG/4 = 65536
    float4 s = make_float4(0.f, 0.f, 0.f, 0.f);
#pragma unroll
    for (int c = 0; c < JCH; ++c) {
        float4 v = ((const float4*)g_part[c])[idx];
        s.x += v.x; s.y += v.y; s.z += v.z; s.w += v.w;
    }
    ((float4*)g_agg)[idx] = s;

    if (idx < NG) {
        float d = 0.f;
#pragma unroll
        for (int c = 0; c < JCH; ++c) d += g_degp[c][idx];
        g_deg[idx] = d;
    }
}

// ============================================================
// GRU elementwise:  out = (1-z)*n + z*h
// ============================================================
__global__ __launch_bounds__(256) void gru_kernel(const float* __restrict__ X,
                                                  float* __restrict__ out)
{
    int idx = blockIdx.x * 256 + threadIdx.x;   // 0..131071
    int i = idx >> 7;
    int d = idx & 127;
    const float* gi = g_gi + (size_t)i * 384;
    const float* gh = g_gh + (size_t)i * 384;
    float r = 1.f / (1.f + __expf(-(gi[d] + gh[d])));
    float z = 1.f / (1.f + __expf(-(gi[128 + d] + gh[128 + d])));
    float n = tanhf(gi[256 + d] + r * gh[256 + d]);
    float hprev = X[idx];
    out[idx] = (1.f - z) * n + z * hprev;
}

// ============================================================
extern "C" void kernel_launch(void* const* d_in, const int* in_sizes, int n_in,
                              void* d_out, int out_size)
{
    (void)in_sizes; (void)n_in; (void)out_size;
    const float* X    = (const float*)d_in[0];   // [1024,128]
    const int*   adj  = (const int*)  d_in[1];   // [1024,1024]
    const float* W1   = (const float*)d_in[2];   // [256,256]
    const float* b1   = (const float*)d_in[3];   // [256]
    const float* W2   = (const float*)d_in[4];   // [128,256]
    const float* b2   = (const float*)d_in[5];   // [128]
    const float* W_ih = (const float*)d_in[6];   // [384,128]
    const float* W_hh = (const float*)d_in[7];   // [384,128]
    const float* b_ih = (const float*)d_in[8];   // [384]
    const float* b_hh = (const float*)d_in[9];   // [384]
    float* out = (float*)d_out;

    float *src, *nbr, *agg, *deg, *msg, *gi, *gh;
    cudaGetSymbolAddress((void**)&src, g_src);
    cudaGetSymbolAddress((void**)&nbr, g_nbr);
    cudaGetSymbolAddress((void**)&agg, g_agg);
    cudaGetSymbolAddress((void**)&deg, g_deg);
    cudaGetSymbolAddress((void**)&msg, g_msg);
    cudaGetSymbolAddress((void**)&gi,  g_gi);
    cudaGetSymbolAddress((void**)&gh,  g_gh);

    // src | nbr | gh in one launch (all depend only on X)
    gemm_fusedX_kernel<<<dim3(14, NG / 64), 256>>>(X, W1, b1, W_hh, b_hh, src, nbr, gh);
    // masked relu aggregation, j-split into JCH partial slabs (+deg partials)
    agg_part_kernel<<<dim3(NG / 8, JCH), 256>>>(adj);
    // sum partials (+ finalize deg)
    agg_reduce_kernel<<<(NG * HG / 4) / 256, 256>>>();
    // msg = agg @ W2^T + deg * b2
    gemm_bias_kernel<<<dim3(DG / 64, NG / 64), 256>>>(agg, HG, W2, HG, b2, deg, msg, DG, HG);
    // gi = msg @ W_ih^T + b_ih
    gemm_bias_kernel<<<dim3(384 / 64, NG / 64), 256>>>(msg, DG, W_ih, DG, b_ih, nullptr, gi, 384, DG);
    // GRU gates + output
    gru_kernel<<<(NG * DG) / 256, 256>>>(X, out);
}